// round 1
// baseline (speedup 1.0000x reference)
#include <cuda_runtime.h>
#include <math.h>

// Problem constants
constexpr int T  = 2048;
constexpr int B  = 64;
constexpr int H  = 128;
constexpr int G  = 512;   // 4*H gate rows
constexpr int IN = 128;   // input width for both layers (126+2 concat, and H)

// ---------------------------------------------------------------------------
// Scratch (static __device__ arrays — no allocation in kernel_launch)
// ---------------------------------------------------------------------------
__device__ float g_xp[T * B * G];   // 256 MB: per-timestep input projections (+bias), reused by both layers
__device__ float g_hs[T * B * H];   // 64 MB: layer-0 hidden states for all timesteps
__device__ float g_hT[B * H];       // final hidden of layer 1

// ---------------------------------------------------------------------------
// Fast transcendentals (abs error ~1e-7, safe vs 1e-3 tolerance)
// ---------------------------------------------------------------------------
__device__ __forceinline__ float sigf(float x) {
    return __fdividef(1.f, 1.f + __expf(-x));
}
__device__ __forceinline__ float tanh_fast(float x) {
    // 1 - 2/(e^{2x}+1); saturates correctly for |x| large (exp->inf/0)
    return 1.f - __fdividef(2.f, __expf(2.f * x) + 1.f);
}

// ---------------------------------------------------------------------------
// Kernel 1/3: input projection GEMM.
//   out[t][b][g] = sum_k A[t][b][k] * Wih[g][k] + bih[g] + bhh[g]
// LAYER==0: A = concat(map_features, positions); LAYER==1: A = g_hs.
// Grid: (T, 8). 512 threads. Tile 64(b) x 64(g), K=128 fully resident.
// ---------------------------------------------------------------------------
constexpr int GEMM_SMEM = 2 * 128 * 68 * 4;   // AsT + BsT, padded rows of 68 floats

template<int LAYER>
__global__ __launch_bounds__(512)
void xproj_gemm(const float* __restrict__ mapf, const float* __restrict__ pos,
                const float* __restrict__ Wih,  const float* __restrict__ bih,
                const float* __restrict__ bhh)
{
    extern __shared__ float sm[];
    float* As = sm;              // [128][68], k-major: As[k*68 + b]
    float* Bs = sm + 128 * 68;   // [128][68], k-major: Bs[k*68 + g]

    const int t   = blockIdx.x;
    const int gc  = blockIdx.y;      // 64-wide gate column block
    const int tid = threadIdx.x;

    // Cooperative load: 64x128 A tile and 64x128 W tile (coalesced gmem reads)
    for (int idx = tid; idx < 64 * 128; idx += 512) {
        const int k = idx & 127;
        const int r = idx >> 7;      // 0..63
        float v;
        if (LAYER == 0) {
            v = (k < 126) ? mapf[(r * T + t) * 126 + k]
                          : pos[(r * T + t) * 2 + (k - 126)];
        } else {
            v = g_hs[(t * B + r) * H + k];
        }
        As[k * 68 + r] = v;
        Bs[k * 68 + r] = Wih[(gc * 64 + r) * IN + k];
    }
    __syncthreads();

    const int bb   = tid >> 3;   // batch row 0..63
    const int gblk = tid & 7;    // 8-wide gate sub-block

    float acc[8];
    #pragma unroll
    for (int i = 0; i < 8; i++) acc[i] = 0.f;

    #pragma unroll 16
    for (int k = 0; k < 128; k++) {
        const float a = As[k * 68 + bb];
        const float4* wp = (const float4*)&Bs[k * 68 + gblk * 8];
        const float4 w0 = wp[0], w1 = wp[1];
        acc[0] += a * w0.x; acc[1] += a * w0.y; acc[2] += a * w0.z; acc[3] += a * w0.w;
        acc[4] += a * w1.x; acc[5] += a * w1.y; acc[6] += a * w1.z; acc[7] += a * w1.w;
    }

    const int gbase = gc * 64 + gblk * 8;
    float4 o0, o1;
    o0.x = acc[0] + bih[gbase + 0] + bhh[gbase + 0];
    o0.y = acc[1] + bih[gbase + 1] + bhh[gbase + 1];
    o0.z = acc[2] + bih[gbase + 2] + bhh[gbase + 2];
    o0.w = acc[3] + bih[gbase + 3] + bhh[gbase + 3];
    o1.x = acc[4] + bih[gbase + 4] + bhh[gbase + 4];
    o1.y = acc[5] + bih[gbase + 5] + bhh[gbase + 5];
    o1.z = acc[6] + bih[gbase + 6] + bhh[gbase + 6];
    o1.w = acc[7] + bih[gbase + 7] + bhh[gbase + 7];
    float* op = g_xp + (t * B + bb) * G + gbase;
    ((float4*)op)[0] = o0;
    ((float4*)op)[1] = o1;
}

// ---------------------------------------------------------------------------
// Kernel 2/4: persistent LSTM recurrence. One CTA per batch row, 256 threads.
// Whh rows 0..255 (i,f gates) live in smem (128 KB, k4-major for conflict-free
// vectorized reads); rows 256..511 (g,o gates) live in registers (32 float4
// per thread). Thread t computes gate rows t and 256+t each step; threads
// 0..127 then do the cell update for their hidden unit (c stays in register).
// ---------------------------------------------------------------------------
constexpr int REC_SMEM = (32 * 256 * 4 + 128 + 512) * 4;   // wq + hbuf + gates

template<bool WRITE_ALL>
__global__ __launch_bounds__(256, 1)
void lstm_rec(const float* __restrict__ Whh)
{
    extern __shared__ float sm[];
    float4* wq   = (float4*)sm;        // [32][256]: wq[k4][row]
    float*  hbuf = sm + 32 * 256 * 4;  // 128 floats (read as float4)
    float*  gates = hbuf + 128;        // 512 floats

    const int tid = threadIdx.x;
    const int b   = blockIdx.x;

    // Register-resident weights: row 256+tid
    float4 wr[32];
    {
        const float4* wrow = (const float4*)(Whh + (256 + tid) * IN);
        #pragma unroll
        for (int k4 = 0; k4 < 32; k4++) wr[k4] = wrow[k4];
    }
    // Shared weights: rows 0..255, k4-major so warp reads are consecutive float4s
    for (int i = tid; i < 256 * 32; i += 256) {
        const int r = i >> 5, k4 = i & 31;
        wq[k4 * 256 + r] = ((const float4*)(Whh + r * IN))[k4];
    }
    if (tid < H) hbuf[tid] = 0.f;
    float c = 0.f;
    __syncthreads();

    const float* xpb = g_xp + b * G;
    float xa = xpb[tid];
    float xb = xpb[256 + tid];

    #pragma unroll 1
    for (int t = 0; t < T; t++) {
        float accA = 0.f, accB = 0.f;
        const float4* h4 = (const float4*)hbuf;
        #pragma unroll
        for (int k4 = 0; k4 < 32; k4++) {
            const float4 hv = h4[k4];
            const float4 wa = wq[k4 * 256 + tid];
            accA += wa.x * hv.x; accA += wa.y * hv.y;
            accA += wa.z * hv.z; accA += wa.w * hv.w;
            const float4 wb = wr[k4];
            accB += wb.x * hv.x; accB += wb.y * hv.y;
            accB += wb.z * hv.z; accB += wb.w * hv.w;
        }
        gates[tid]       = accA + xa;
        gates[256 + tid] = accB + xb;
        // Prefetch next step's xproj (fully hidden behind next dot loop)
        if (t + 1 < T) {
            const float* nx = xpb + (t + 1) * (B * G);
            xa = nx[tid];
            xb = nx[256 + tid];
        }
        __syncthreads();
        if (tid < H) {
            const float ig = sigf(gates[tid]);
            const float fg = sigf(gates[H + tid]);
            const float gg = tanh_fast(gates[2 * H + tid]);
            const float og = sigf(gates[3 * H + tid]);
            c = fg * c + ig * gg;
            const float h = og * tanh_fast(c);
            hbuf[tid] = h;
            if (WRITE_ALL) {
                g_hs[(t * B + b) * H + tid] = h;
            } else if (t == T - 1) {
                g_hT[b * H + tid] = h;
            }
        }
        __syncthreads();
    }
}

// ---------------------------------------------------------------------------
// Kernel 5: MLP head. One CTA per batch row, 64 threads.
//   h = hT1 @ W1.T + b1 -> LayerNorm -> LeakyReLU(0.2) -> @ W2.T + b2
// ---------------------------------------------------------------------------
__global__ void head_kernel(const float* __restrict__ W1, const float* __restrict__ b1,
                            const float* __restrict__ lng, const float* __restrict__ lnb,
                            const float* __restrict__ W2, const float* __restrict__ b2,
                            float* __restrict__ out)
{
    __shared__ float hb[128];
    __shared__ float red[64];
    __shared__ float bc;
    const int b = blockIdx.x;
    const int j = threadIdx.x;

    hb[j]      = g_hT[b * H + j];
    hb[j + 64] = g_hT[b * H + 64 + j];
    __syncthreads();

    float acc = b1[j];
    #pragma unroll 8
    for (int k = 0; k < H; k++) acc += hb[k] * W1[j * H + k];

    // mean
    red[j] = acc; __syncthreads();
    if (j == 0) { float s = 0.f; for (int k = 0; k < 64; k++) s += red[k]; bc = s * (1.f / 64.f); }
    __syncthreads();
    const float mu = bc;
    const float d  = acc - mu;

    // variance
    red[j] = d * d; __syncthreads();
    if (j == 0) { float s = 0.f; for (int k = 0; k < 64; k++) s += red[k]; bc = s * (1.f / 64.f); }
    __syncthreads();
    const float var = bc;

    float v = d * rsqrtf(var + 1e-5f) * lng[j] + lnb[j];
    v = (v >= 0.f) ? v : 0.2f * v;   // LeakyReLU(0.2)

    red[j] = v * W2[j]; __syncthreads();
    if (j == 0) { float s = 0.f; for (int k = 0; k < 64; k++) s += red[k]; out[b] = s + b2[0]; }
}

// ---------------------------------------------------------------------------
// Launch: gemm0 -> rec0 -> gemm1 -> rec1 -> head (in-order default stream)
// ---------------------------------------------------------------------------
extern "C" void kernel_launch(void* const* d_in, const int* in_sizes, int n_in,
                              void* d_out, int out_size)
{
    const float* mapf = (const float*)d_in[0];
    const float* pos  = (const float*)d_in[1];
    const float* Wih0 = (const float*)d_in[2];
    const float* Whh0 = (const float*)d_in[3];
    const float* bih0 = (const float*)d_in[4];
    const float* bhh0 = (const float*)d_in[5];
    const float* Wih1 = (const float*)d_in[6];
    const float* Whh1 = (const float*)d_in[7];
    const float* bih1 = (const float*)d_in[8];
    const float* bhh1 = (const float*)d_in[9];
    const float* W1   = (const float*)d_in[10];
    const float* b1   = (const float*)d_in[11];
    const float* lng  = (const float*)d_in[12];
    const float* lnb  = (const float*)d_in[13];
    const float* W2   = (const float*)d_in[14];
    const float* b2   = (const float*)d_in[15];
    float* out = (float*)d_out;

    cudaFuncSetAttribute((const void*)xproj_gemm<0>,
                         cudaFuncAttributeMaxDynamicSharedMemorySize, GEMM_SMEM);
    cudaFuncSetAttribute((const void*)xproj_gemm<1>,
                         cudaFuncAttributeMaxDynamicSharedMemorySize, GEMM_SMEM);
    cudaFuncSetAttribute((const void*)lstm_rec<true>,
                         cudaFuncAttributeMaxDynamicSharedMemorySize, REC_SMEM);
    cudaFuncSetAttribute((const void*)lstm_rec<false>,
                         cudaFuncAttributeMaxDynamicSharedMemorySize, REC_SMEM);

    dim3 gg(T, 8);
    xproj_gemm<0><<<gg, 512, GEMM_SMEM>>>(mapf, pos, Wih0, bih0, bhh0);
    lstm_rec<true><<<B, 256, REC_SMEM>>>(Whh0);            // writes g_hs
    xproj_gemm<1><<<gg, 512, GEMM_SMEM>>>(mapf, pos, Wih1, bih1, bhh1);  // reads g_hs
    lstm_rec<false><<<B, 256, REC_SMEM>>>(Whh1);           // writes g_hT
    head_kernel<<<B, 64>>>(W1, b1, lng, lnb, W2, b2, out);
}

// round 4
// speedup vs baseline: 1.2007x; 1.2007x over previous
#include <cuda_runtime.h>
#include <math.h>

// Problem constants
constexpr int T  = 2048;
constexpr int B  = 64;
constexpr int H  = 128;
constexpr int G  = 512;   // 4*H gate rows
constexpr int IN = 128;

typedef unsigned long long u64;

// ---------------------------------------------------------------------------
// Scratch (static __device__ arrays — no allocation in kernel_launch)
// ---------------------------------------------------------------------------
__device__ float g_xp[(size_t)T * B * G];   // 256 MB: xproj (+bias) per timestep
__device__ float g_hs[(size_t)T * B * H];   // 64 MB: layer-0 hidden states
__device__ float g_hT[B * H];               // final hidden of layer 1

// ---------------------------------------------------------------------------
// Packed fp32x2 helpers (PTX ISA 8.6+, sm_100+)
// ---------------------------------------------------------------------------
__device__ __forceinline__ u64 ffma2(u64 a, u64 b, u64 c) {
    u64 d;
    asm("fma.rn.f32x2 %0, %1, %2, %3;" : "=l"(d) : "l"(a), "l"(b), "l"(c));
    return d;
}
__device__ __forceinline__ u64 pack_dup(float a) {
    u64 d; asm("mov.b64 %0, {%1, %1};" : "=l"(d) : "f"(a)); return d;
}
__device__ __forceinline__ u64 pack2(float x, float y) {
    u64 d; asm("mov.b64 %0, {%1, %2};" : "=l"(d) : "f"(x), "f"(y)); return d;
}
__device__ __forceinline__ float2 unpack2(u64 a) {
    float2 r; asm("mov.b64 {%0, %1}, %2;" : "=f"(r.x), "=f"(r.y) : "l"(a)); return r;
}
__device__ __forceinline__ float hadd2(u64 a) {
    float2 r = unpack2(a); return r.x + r.y;
}

// Fast transcendentals (validated R1: rel_err 5.5e-7 end-to-end)
__device__ __forceinline__ float sigf(float x) {
    return __fdividef(1.f, 1.f + __expf(-x));
}
__device__ __forceinline__ float tanh_fast(float x) {
    return 1.f - __fdividef(2.f, __expf(2.f * x) + 1.f);
}

// ---------------------------------------------------------------------------
// Kernel: input projection GEMM. out[t][b][g] = A[t][b][:]·Wih[g][:] + bih+bhh
// Grid (T, 8), 256 threads. Tile 64(b) x 64(g), K=128. 2x8 outputs/thread,
// packed f32x2 FMAs (B pairs along g are natural f32x2 operands).
// ---------------------------------------------------------------------------
constexpr int GEMM_SMEM = 2 * 128 * 68 * 4;   // As + Bs, padded rows of 68

template<int LAYER>
__global__ __launch_bounds__(256)
void xproj_gemm(const float* __restrict__ mapf, const float* __restrict__ pos,
                const float* __restrict__ Wih,  const float* __restrict__ bih,
                const float* __restrict__ bhh)
{
    extern __shared__ float sm[];
    float* As = sm;              // [128][68] k-major: As[k*68 + b]
    float* Bs = sm + 128 * 68;   // [128][68] k-major: Bs[k*68 + g]

    const int t   = blockIdx.x;
    const int gc  = blockIdx.y;
    const int tid = threadIdx.x;

    for (int idx = tid; idx < 64 * 128; idx += 256) {
        const int k = idx & 127;
        const int r = idx >> 7;
        float v;
        if (LAYER == 0) {
            v = (k < 126) ? mapf[((size_t)r * T + t) * 126 + k]
                          : pos[((size_t)r * T + t) * 2 + (k - 126)];
        } else {
            v = g_hs[((size_t)t * B + r) * H + k];
        }
        As[k * 68 + r] = v;
        Bs[k * 68 + r] = Wih[(gc * 64 + r) * IN + k];
    }
    __syncthreads();

    const int bb   = tid >> 3;   // 0..31 (also handles bb+32)
    const int gblk = tid & 7;    // 8-wide gate sub-block

    u64 acc[8];
    #pragma unroll
    for (int i = 0; i < 8; i++) acc[i] = 0ull;

    #pragma unroll 8
    for (int k = 0; k < 128; k++) {
        const u64 a0 = pack_dup(As[k * 68 + bb]);
        const u64 a1 = pack_dup(As[k * 68 + bb + 32]);
        const u64* wp = (const u64*)&Bs[k * 68 + gblk * 8];   // 16B aligned
        const u64 w0 = wp[0], w1 = wp[1], w2 = wp[2], w3 = wp[3];
        acc[0] = ffma2(w0, a0, acc[0]);
        acc[1] = ffma2(w1, a0, acc[1]);
        acc[2] = ffma2(w2, a0, acc[2]);
        acc[3] = ffma2(w3, a0, acc[3]);
        acc[4] = ffma2(w0, a1, acc[4]);
        acc[5] = ffma2(w1, a1, acc[5]);
        acc[6] = ffma2(w2, a1, acc[6]);
        acc[7] = ffma2(w3, a1, acc[7]);
    }

    const int gbase = gc * 64 + gblk * 8;
    float bias[8];
    #pragma unroll
    for (int i = 0; i < 8; i++) bias[i] = bih[gbase + i] + bhh[gbase + i];

    #pragma unroll
    for (int half = 0; half < 2; half++) {
        const int row = bb + half * 32;
        float4 o0, o1;
        float2 p0 = unpack2(acc[half * 4 + 0]);
        float2 p1 = unpack2(acc[half * 4 + 1]);
        float2 p2 = unpack2(acc[half * 4 + 2]);
        float2 p3 = unpack2(acc[half * 4 + 3]);
        o0.x = p0.x + bias[0]; o0.y = p0.y + bias[1];
        o0.z = p1.x + bias[2]; o0.w = p1.y + bias[3];
        o1.x = p2.x + bias[4]; o1.y = p2.y + bias[5];
        o1.z = p3.x + bias[6]; o1.w = p3.y + bias[7];
        float* op = g_xp + ((size_t)t * B + row) * G + gbase;
        ((float4*)op)[0] = o0;
        ((float4*)op)[1] = o1;
    }
}

// ---------------------------------------------------------------------------
// Kernel: persistent LSTM recurrence. One CTA per batch row, 512 threads,
// one gate row per thread. Whh[g][0..79] in 40 packed f32x2 regs (80 fp32
// regs); Whh[g][80..127] (12 float4) in smem, [k4][512] layout.
// Each thread activates its own gate pre-barrier; threads 0..127 update c,h.
// ---------------------------------------------------------------------------
constexpr int REC_SMEM = (12 * 512 * 4 + 128 + 512) * 4;   // wsm + hbuf + gates

template<bool WRITE_ALL>
__global__ __launch_bounds__(512, 1)
void lstm_rec(const float* __restrict__ Whh)
{
    extern __shared__ float sm[];
    float4* wsm  = (float4*)sm;           // [12][512]: cols 80..127 of each row
    float*  hbuf = sm + 12 * 512 * 4;     // 128 floats
    float*  gates = hbuf + 128;           // 512 floats (activated)

    const int tid = threadIdx.x;
    const int b   = blockIdx.x;

    // Register-resident weights: cols 0..79 as 40 packed f32x2
    u64 wr[40];
    {
        const u64* wrow = (const u64*)(Whh + tid * IN);
        #pragma unroll
        for (int i = 0; i < 40; i++) wr[i] = wrow[i];
    }
    // Tail cols 80..127 to smem
    {
        const float4* wtail = (const float4*)(Whh + tid * IN + 80);
        #pragma unroll
        for (int k4 = 0; k4 < 12; k4++) wsm[k4 * 512 + tid] = wtail[k4];
    }
    if (tid < H) hbuf[tid] = 0.f;
    float c = 0.f;

    const float* xpb = g_xp + (size_t)b * G;
    float x = xpb[tid];
    const int gtype = tid >> 7;   // 0:i 1:f 2:g 3:o  (warp-uniform)
    __syncthreads();

    #pragma unroll 1
    for (int t = 0; t < T; t++) {
        const u64* h2 = (const u64*)hbuf;   // 64 packed pairs
        u64 acc0 = 0ull, acc1 = 0ull, acc2 = 0ull, acc3 = 0ull;
        #pragma unroll
        for (int i = 0; i < 40; i += 4) {
            acc0 = ffma2(wr[i],     h2[i],     acc0);
            acc1 = ffma2(wr[i + 1], h2[i + 1], acc1);
            acc2 = ffma2(wr[i + 2], h2[i + 2], acc2);
            acc3 = ffma2(wr[i + 3], h2[i + 3], acc3);
        }
        #pragma unroll
        for (int k4 = 0; k4 < 12; k4++) {
            const float4 w = wsm[k4 * 512 + tid];
            acc0 = ffma2(pack2(w.x, w.y), h2[40 + 2 * k4],     acc0);
            acc1 = ffma2(pack2(w.z, w.w), h2[40 + 2 * k4 + 1], acc1);
        }
        const float a = hadd2(acc0) + hadd2(acc1) + hadd2(acc2) + hadd2(acc3) + x;
        const float act = (gtype == 2) ? tanh_fast(a) : sigf(a);
        // prefetch next step's xproj (hidden behind epilogue + next dot)
        if (t + 1 < T) x = xpb[(size_t)(t + 1) * (B * G) + tid];
        gates[tid] = act;
        __syncthreads();
        if (tid < H) {
            const float ig = gates[tid];
            const float fg = gates[H + tid];
            const float gg = gates[2 * H + tid];
            const float og = gates[3 * H + tid];
            c = fg * c + ig * gg;
            const float h = og * tanh_fast(c);
            hbuf[tid] = h;
            if (WRITE_ALL) {
                g_hs[((size_t)t * B + b) * H + tid] = h;
            } else if (t == T - 1) {
                g_hT[b * H + tid] = h;
            }
        }
        __syncthreads();
    }
}

// ---------------------------------------------------------------------------
// MLP head: one CTA per batch row, 64 threads.
// ---------------------------------------------------------------------------
__global__ void head_kernel(const float* __restrict__ W1, const float* __restrict__ b1,
                            const float* __restrict__ lng, const float* __restrict__ lnb,
                            const float* __restrict__ W2, const float* __restrict__ b2,
                            float* __restrict__ out)
{
    __shared__ float hb[128];
    __shared__ float red[64];
    __shared__ float bc;
    const int b = blockIdx.x;
    const int j = threadIdx.x;

    hb[j]      = g_hT[b * H + j];
    hb[j + 64] = g_hT[b * H + 64 + j];
    __syncthreads();

    float acc = b1[j];
    #pragma unroll 8
    for (int k = 0; k < H; k++) acc += hb[k] * W1[j * H + k];

    red[j] = acc; __syncthreads();
    if (j == 0) { float s = 0.f; for (int k = 0; k < 64; k++) s += red[k]; bc = s * (1.f / 64.f); }
    __syncthreads();
    const float mu = bc;
    const float d  = acc - mu;

    red[j] = d * d; __syncthreads();
    if (j == 0) { float s = 0.f; for (int k = 0; k < 64; k++) s += red[k]; bc = s * (1.f / 64.f); }
    __syncthreads();
    const float var = bc;

    float v = d * rsqrtf(var + 1e-5f) * lng[j] + lnb[j];
    v = (v >= 0.f) ? v : 0.2f * v;

    red[j] = v * W2[j]; __syncthreads();
    if (j == 0) { float s = 0.f; for (int k = 0; k < 64; k++) s += red[k]; out[b] = s + b2[0]; }
}

// ---------------------------------------------------------------------------
// Launch: gemm0 -> rec0 -> gemm1 -> rec1 -> head
// ---------------------------------------------------------------------------
extern "C" void kernel_launch(void* const* d_in, const int* in_sizes, int n_in,
                              void* d_out, int out_size)
{
    const float* mapf = (const float*)d_in[0];
    const float* pos  = (const float*)d_in[1];
    const float* Wih0 = (const float*)d_in[2];
    const float* Whh0 = (const float*)d_in[3];
    const float* bih0 = (const float*)d_in[4];
    const float* bhh0 = (const float*)d_in[5];
    const float* Wih1 = (const float*)d_in[6];
    const float* Whh1 = (const float*)d_in[7];
    const float* bih1 = (const float*)d_in[8];
    const float* bhh1 = (const float*)d_in[9];
    const float* W1   = (const float*)d_in[10];
    const float* b1   = (const float*)d_in[11];
    const float* lng  = (const float*)d_in[12];
    const float* lnb  = (const float*)d_in[13];
    const float* W2   = (const float*)d_in[14];
    const float* b2   = (const float*)d_in[15];
    float* out = (float*)d_out;

    cudaFuncSetAttribute((const void*)xproj_gemm<0>,
                         cudaFuncAttributeMaxDynamicSharedMemorySize, GEMM_SMEM);
    cudaFuncSetAttribute((const void*)xproj_gemm<1>,
                         cudaFuncAttributeMaxDynamicSharedMemorySize, GEMM_SMEM);
    cudaFuncSetAttribute((const void*)lstm_rec<true>,
                         cudaFuncAttributeMaxDynamicSharedMemorySize, REC_SMEM);
    cudaFuncSetAttribute((const void*)lstm_rec<false>,
                         cudaFuncAttributeMaxDynamicSharedMemorySize, REC_SMEM);

    dim3 gg(T, 8);
    xproj_gemm<0><<<gg, 256, GEMM_SMEM>>>(mapf, pos, Wih0, bih0, bhh0);
    lstm_rec<true><<<B, 512, REC_SMEM>>>(Whh0);
    xproj_gemm<1><<<gg, 256, GEMM_SMEM>>>(mapf, pos, Wih1, bih1, bhh1);
    lstm_rec<false><<<B, 512, REC_SMEM>>>(Whh1);
    head_kernel<<<B, 64>>>(W1, b1, lng, lnb, W2, b2, out);
}

// round 7
// speedup vs baseline: 1.4396x; 1.1990x over previous
#include <cuda_runtime.h>
#include <math.h>

// Problem constants
constexpr int T  = 2048;
constexpr int B  = 64;
constexpr int H  = 128;
constexpr int G  = 512;   // 4*H gate rows
constexpr int IN = 128;

typedef unsigned long long u64;

// ---------------------------------------------------------------------------
// Scratch (static __device__ arrays — no allocation in kernel_launch)
// ---------------------------------------------------------------------------
__device__ float g_xp[(size_t)T * B * G];   // 256 MB: xproj (+bias) per timestep
__device__ float g_hs[(size_t)T * B * H];   // 64 MB: layer-0 hidden states
__device__ float g_hT[B * H];               // final hidden of layer 1

// ---------------------------------------------------------------------------
// Packed fp32x2 helpers (PTX ISA 8.6+, sm_100+)
// ---------------------------------------------------------------------------
__device__ __forceinline__ u64 ffma2(u64 a, u64 b, u64 c) {
    u64 d;
    asm("fma.rn.f32x2 %0, %1, %2, %3;" : "=l"(d) : "l"(a), "l"(b), "l"(c));
    return d;
}
__device__ __forceinline__ u64 pack_dup(float a) {
    u64 d; asm("mov.b64 %0, {%1, %1};" : "=l"(d) : "f"(a)); return d;
}
__device__ __forceinline__ u64 pack2(float x, float y) {
    u64 d; asm("mov.b64 %0, {%1, %2};" : "=l"(d) : "f"(x), "f"(y)); return d;
}
__device__ __forceinline__ float2 unpack2(u64 a) {
    float2 r; asm("mov.b64 {%0, %1}, %2;" : "=f"(r.x), "=f"(r.y) : "l"(a)); return r;
}
__device__ __forceinline__ float hadd2(u64 a) {
    float2 r = unpack2(a); return r.x + r.y;
}

// Fast transcendentals (validated: rel_err ~5e-7 end-to-end)
__device__ __forceinline__ float sigf(float x) {
    return __fdividef(1.f, 1.f + __expf(-x));
}
__device__ __forceinline__ float tanh_fast(float x) {
    return 1.f - __fdividef(2.f, __expf(2.f * x) + 1.f);
}

// ---------------------------------------------------------------------------
// Kernel: input projection GEMM, 4 timesteps per CTA (W tile stays resident).
//   out[t][b][g] = A[t][b][:]·Wih[g][:] + bih[g]+bhh[g]
// Grid (T/4, 8), 256 threads. Tile 64(b) x 64(g), K=128.
// ---------------------------------------------------------------------------
constexpr int TT = 4;                         // timesteps per CTA
constexpr int GEMM_SMEM = (128 * 68 + 64 * 136) * 4;   // Ws + As = 69,632 B

template<int LAYER>
__global__ __launch_bounds__(256)
void xproj_gemm(const float* __restrict__ mapf, const float* __restrict__ pos,
                const float* __restrict__ Wih,  const float* __restrict__ bih,
                const float* __restrict__ bhh)
{
    extern __shared__ float sm[];
    float* Ws = sm;               // [128][68] k-major: Ws[k*68 + g]
    float* As = sm + 128 * 68;    // [64][136] row-major: As[b*136 + k]

    const int t0  = blockIdx.x * TT;
    const int gc  = blockIdx.y;
    const int tid = threadIdx.x;

    // Load W tile once (reused for TT timesteps)
    for (int idx = tid; idx < 64 * 128; idx += 256) {
        const int k = idx & 127;
        const int g = idx >> 7;
        Ws[k * 68 + g] = Wih[(gc * 64 + g) * IN + k];
    }

    const int bb   = tid >> 3;   // 0..31 (also handles bb+32)
    const int gblk = tid & 7;
    const int gbase = gc * 64 + gblk * 8;
    float bias[8];
    #pragma unroll
    for (int i = 0; i < 8; i++) bias[i] = bih[gbase + i] + bhh[gbase + i];

    for (int tt = 0; tt < TT; tt++) {
        const int t = t0 + tt;
        __syncthreads();   // protects As reuse (and Ws on first pass)
        for (int idx = tid; idx < 64 * 128; idx += 256) {
            const int k = idx & 127;
            const int r = idx >> 7;
            float v;
            if (LAYER == 0) {
                v = (k < 126) ? mapf[((size_t)r * T + t) * 126 + k]
                              : pos[((size_t)r * T + t) * 2 + (k - 126)];
            } else {
                v = g_hs[((size_t)t * B + r) * H + k];
            }
            As[r * 136 + k] = v;
        }
        __syncthreads();

        u64 acc[8];
        #pragma unroll
        for (int i = 0; i < 8; i++) acc[i] = 0ull;

        #pragma unroll 8
        for (int k = 0; k < 128; k++) {
            const u64 a0 = pack_dup(As[bb * 136 + k]);
            const u64 a1 = pack_dup(As[(bb + 32) * 136 + k]);
            const u64* wp = (const u64*)&Ws[k * 68 + gblk * 8];   // 16B aligned
            const u64 w0 = wp[0], w1 = wp[1], w2 = wp[2], w3 = wp[3];
            acc[0] = ffma2(w0, a0, acc[0]);
            acc[1] = ffma2(w1, a0, acc[1]);
            acc[2] = ffma2(w2, a0, acc[2]);
            acc[3] = ffma2(w3, a0, acc[3]);
            acc[4] = ffma2(w0, a1, acc[4]);
            acc[5] = ffma2(w1, a1, acc[5]);
            acc[6] = ffma2(w2, a1, acc[6]);
            acc[7] = ffma2(w3, a1, acc[7]);
        }

        #pragma unroll
        for (int half = 0; half < 2; half++) {
            const int row = bb + half * 32;
            float4 o0, o1;
            float2 p0 = unpack2(acc[half * 4 + 0]);
            float2 p1 = unpack2(acc[half * 4 + 1]);
            float2 p2 = unpack2(acc[half * 4 + 2]);
            float2 p3 = unpack2(acc[half * 4 + 3]);
            o0.x = p0.x + bias[0]; o0.y = p0.y + bias[1];
            o0.z = p1.x + bias[2]; o0.w = p1.y + bias[3];
            o1.x = p2.x + bias[4]; o1.y = p2.y + bias[5];
            o1.z = p3.x + bias[6]; o1.w = p3.y + bias[7];
            float* op = g_xp + ((size_t)t * B + row) * G + gbase;
            ((float4*)op)[0] = o0;
            ((float4*)op)[1] = o1;
        }
    }
}

// ---------------------------------------------------------------------------
// Kernel: persistent LSTM recurrence. One CTA per batch row, 256 threads,
// TWO gate rows per thread (rows tid and 256+tid). Columns 0..83 of both rows
// in registers (42 u64 = 84 fp32 regs per row, 168 total — safe margin under
// the 255/thread cap); columns 84..127 (11 float4 per row) in smem. h read as
// float4 and reused for both rows. 8 warps -> low barrier/arbiter spread.
//   rows 0..127=i, 128..255=f (sigmoid); 256..383=g (tanh), 384..511=o.
// ---------------------------------------------------------------------------
constexpr int REC_SMEM = (11 * 2 * 256 * 4 + 128 + 512) * 4;   // wsm + hbuf + gates

template<bool WRITE_ALL>
__global__ __launch_bounds__(256, 1)
void lstm_rec(const float* __restrict__ Whh)
{
    extern __shared__ float sm[];
    float4* wsm  = (float4*)sm;            // [(q*2+half)*256 + tid], q=0..10
    float*  hbuf = sm + 11 * 2 * 256 * 4;  // 128 floats
    float*  gates = hbuf + 128;            // 512 floats (activated)

    const int tid  = threadIdx.x;
    const int b    = blockIdx.x;
    const int rowA = tid;         // i (tid<128) or f gate
    const int rowB = 256 + tid;   // g (tid<128) or o gate

    // Register-resident weights: cols 0..83 of both rows (42 u64 each)
    u64 wrA[42], wrB[42];
    {
        const u64* pa = (const u64*)(Whh + rowA * IN);
        const u64* pb = (const u64*)(Whh + rowB * IN);
        #pragma unroll
        for (int i = 0; i < 42; i++) { wrA[i] = pa[i]; wrB[i] = pb[i]; }
    }
    // Tail cols 84..127 (11 float4 per row) to smem
    {
        const float4* ta = (const float4*)(Whh + rowA * IN + 84);
        const float4* tb = (const float4*)(Whh + rowB * IN + 84);
        #pragma unroll
        for (int q = 0; q < 11; q++) {
            wsm[(q * 2 + 0) * 256 + tid] = ta[q];
            wsm[(q * 2 + 1) * 256 + tid] = tb[q];
        }
    }
    if (tid < H) hbuf[tid] = 0.f;
    float c = 0.f;

    const float* xpb = g_xp + (size_t)b * G;
    float xa = xpb[rowA];
    float xb = xpb[rowB];
    const bool tanhB = (tid < 128);   // rowB in g-gate range
    __syncthreads();

    #pragma unroll 1
    for (int t = 0; t < T; t++) {
        const float4* hb4 = (const float4*)hbuf;   // 32 float4
        u64 a0 = 0ull, a1 = 0ull, b0 = 0ull, b1 = 0ull;
        // cols 0..83 from registers (21 float4-chunks of h)
        #pragma unroll
        for (int q = 0; q < 21; q++) {
            const float4 hv = hb4[q];
            const u64 hlo = pack2(hv.x, hv.y);
            const u64 hhi = pack2(hv.z, hv.w);
            a0 = ffma2(wrA[2 * q],     hlo, a0);
            a1 = ffma2(wrA[2 * q + 1], hhi, a1);
            b0 = ffma2(wrB[2 * q],     hlo, b0);
            b1 = ffma2(wrB[2 * q + 1], hhi, b1);
        }
        // cols 84..127 from smem (11 float4-chunks per row)
        #pragma unroll
        for (int q = 0; q < 11; q++) {
            const float4 hv = hb4[21 + q];
            const u64 hlo = pack2(hv.x, hv.y);
            const u64 hhi = pack2(hv.z, hv.w);
            const float4 wa = wsm[(q * 2 + 0) * 256 + tid];
            const float4 wb = wsm[(q * 2 + 1) * 256 + tid];
            a0 = ffma2(pack2(wa.x, wa.y), hlo, a0);
            a1 = ffma2(pack2(wa.z, wa.w), hhi, a1);
            b0 = ffma2(pack2(wb.x, wb.y), hlo, b0);
            b1 = ffma2(pack2(wb.z, wb.w), hhi, b1);
        }
        const float aA = hadd2(a0) + hadd2(a1) + xa;
        const float aB = hadd2(b0) + hadd2(b1) + xb;
        const float actA = sigf(aA);                              // i or f
        const float actB = tanhB ? tanh_fast(aB) : sigf(aB);      // g or o
        // prefetch next step's xproj (hidden behind next dot)
        if (t + 1 < T) {
            const float* nx = xpb + (size_t)(t + 1) * (B * G);
            xa = nx[rowA];
            xb = nx[rowB];
        }
        gates[rowA] = actA;
        gates[rowB] = actB;
        __syncthreads();
        if (tid < H) {
            const float ig = gates[tid];
            const float fg = gates[H + tid];
            const float gg = gates[2 * H + tid];
            const float og = gates[3 * H + tid];
            c = fg * c + ig * gg;
            const float h = og * tanh_fast(c);
            hbuf[tid] = h;
            if (WRITE_ALL) {
                g_hs[((size_t)t * B + b) * H + tid] = h;
            } else if (t == T - 1) {
                g_hT[b * H + tid] = h;
            }
        }
        __syncthreads();
    }
}

// ---------------------------------------------------------------------------
// MLP head: one CTA per batch row, 64 threads.
// ---------------------------------------------------------------------------
__global__ void head_kernel(const float* __restrict__ W1, const float* __restrict__ b1,
                            const float* __restrict__ lng, const float* __restrict__ lnb,
                            const float* __restrict__ W2, const float* __restrict__ b2,
                            float* __restrict__ out)
{
    __shared__ float hb[128];
    __shared__ float red[64];
    __shared__ float bc;
    const int b = blockIdx.x;
    const int j = threadIdx.x;

    hb[j]      = g_hT[b * H + j];
    hb[j + 64] = g_hT[b * H + 64 + j];
    __syncthreads();

    float acc = b1[j];
    #pragma unroll 8
    for (int k = 0; k < H; k++) acc += hb[k] * W1[j * H + k];

    red[j] = acc; __syncthreads();
    if (j == 0) { float s = 0.f; for (int k = 0; k < 64; k++) s += red[k]; bc = s * (1.f / 64.f); }
    __syncthreads();
    const float mu = bc;
    const float d  = acc - mu;

    red[j] = d * d; __syncthreads();
    if (j == 0) { float s = 0.f; for (int k = 0; k < 64; k++) s += red[k]; bc = s * (1.f / 64.f); }
    __syncthreads();
    const float var = bc;

    float v = d * rsqrtf(var + 1e-5f) * lng[j] + lnb[j];
    v = (v >= 0.f) ? v : 0.2f * v;

    red[j] = v * W2[j]; __syncthreads();
    if (j == 0) { float s = 0.f; for (int k = 0; k < 64; k++) s += red[k]; out[b] = s + b2[0]; }
}

// ---------------------------------------------------------------------------
// Launch: gemm0 -> rec0 -> gemm1 -> rec1 -> head
// ---------------------------------------------------------------------------
extern "C" void kernel_launch(void* const* d_in, const int* in_sizes, int n_in,
                              void* d_out, int out_size)
{
    const float* mapf = (const float*)d_in[0];
    const float* pos  = (const float*)d_in[1];
    const float* Wih0 = (const float*)d_in[2];
    const float* Whh0 = (const float*)d_in[3];
    const float* bih0 = (const float*)d_in[4];
    const float* bhh0 = (const float*)d_in[5];
    const float* Wih1 = (const float*)d_in[6];
    const float* Whh1 = (const float*)d_in[7];
    const float* bih1 = (const float*)d_in[8];
    const float* bhh1 = (const float*)d_in[9];
    const float* W1   = (const float*)d_in[10];
    const float* b1   = (const float*)d_in[11];
    const float* lng  = (const float*)d_in[12];
    const float* lnb  = (const float*)d_in[13];
    const float* W2   = (const float*)d_in[14];
    const float* b2   = (const float*)d_in[15];
    float* out = (float*)d_out;

    cudaFuncSetAttribute((const void*)xproj_gemm<0>,
                         cudaFuncAttributeMaxDynamicSharedMemorySize, GEMM_SMEM);
    cudaFuncSetAttribute((const void*)xproj_gemm<1>,
                         cudaFuncAttributeMaxDynamicSharedMemorySize, GEMM_SMEM);
    cudaFuncSetAttribute((const void*)lstm_rec<true>,
                         cudaFuncAttributeMaxDynamicSharedMemorySize, REC_SMEM);
    cudaFuncSetAttribute((const void*)lstm_rec<false>,
                         cudaFuncAttributeMaxDynamicSharedMemorySize, REC_SMEM);

    dim3 gg(T / TT, 8);
    xproj_gemm<0><<<gg, 256, GEMM_SMEM>>>(mapf, pos, Wih0, bih0, bhh0);
    lstm_rec<true><<<B, 256, REC_SMEM>>>(Whh0);
    xproj_gemm<1><<<gg, 256, GEMM_SMEM>>>(mapf, pos, Wih1, bih1, bhh1);
    lstm_rec<false><<<B, 256, REC_SMEM>>>(Whh1);
    head_kernel<<<B, 64>>>(W1, b1, lng, lnb, W2, b2, out);
}